// round 8
// baseline (speedup 1.0000x reference)
#include <cuda_runtime.h>

#define Wd 256
#define Hd 256
#define Bd 64
#define NPIX (Bd*Hd*Wd)
#define HIMG 32
#define HPIX (HIMG*Hd*Wd)
#define NVH  (HPIX/4)
#define SEG  4
#define EPSf 1e-12f
#define FULLM 0xffffffffu

// ---- iteration-invariant scratch ----
__device__ __align__(16) float g_g2x[NPIX];
__device__ __align__(16) float g_g2y[NPIX];
__device__ __align__(16) float g_rc [NPIX];
// ---- double-buffered dual state ----
__device__ __align__(16) float g_p11[2][NPIX];
__device__ __align__(16) float g_p12[2][NPIX];
__device__ __align__(16) float g_p21[2][NPIX];
__device__ __align__(16) float g_p22[2][NPIX];
// ---- u scratch (ping-pongs with d_out) ----
__device__ __align__(16) float g_u1s[NPIX];
__device__ __align__(16) float g_u2s[NPIX];

union F4 { float4 v; float f[4]; };
__device__ __forceinline__ float4 ld4(const float* p) { return *reinterpret_cast<const float4*>(p); }
__device__ __forceinline__ void   st4(float* p, float4 v) { *reinterpret_cast<float4*>(p) = v; }
__device__ __forceinline__ F4 zf4() { F4 a; a.v = make_float4(0,0,0,0); return a; }

// u' = u + v(u) + ts*div(p)   (one pixel)
__device__ __forceinline__ void u_lane(
    float u1, float u2, float gx, float gy, float rc,
    float p11, float p11L, float p12, float p12U,
    float p21, float p21L, float p22, float p22U,
    bool j0, bool i0, float ts, float l_t,
    float& o1, float& o2)
{
    float dx1 = j0 ? p11 : (p11 - p11L);
    float dx2 = j0 ? p21 : (p21 - p21L);
    float dy1 = i0 ? p12 : (p12 - p12U);
    float dy2 = i0 ? p22 : (p22 - p22U);
    float rho  = rc + gx * u1 + gy * u2 + EPSf;
    float grad = gx * gx + gy * gy + EPSf;
    float lg   = l_t * grad;
    float v1, v2;
    if      (rho < -lg)   { v1 =  l_t * gx; v2 =  l_t * gy; }
    else if (rho >  lg)   { v1 = -l_t * gx; v2 = -l_t * gy; }
    else if (grad > EPSf) { float s = -rho / grad; v1 = s * gx; v2 = s * gy; }
    else                  { v1 = 0.f; v2 = 0.f; }
    o1 = u1 + v1 + ts * (dx1 + dy1);
    o2 = u2 + v2 + ts * (dx2 + dy2);
}

// p' = (p + taut*grad_u) / (1 + taut*|grad_u|)   (one pixel)
__device__ __forceinline__ void p_lane(
    float uC1, float uR1, float uD1, float uC2, float uR2, float uD2,
    bool hasR, bool hasD, float taut,
    float p11, float p12, float p21, float p22,
    float& o11, float& o12, float& o21, float& o22)
{
    float u1x = hasR ? (uR1 - uC1) : 0.f;
    float u2x = hasR ? (uR2 - uC2) : 0.f;
    float u1y = hasD ? (uD1 - uC1) : 0.f;
    float u2y = hasD ? (uD2 - uC2) : 0.f;
    float n1 = sqrtf(u1x*u1x + u1y*u1y + EPSf);
    float n2 = sqrtf(u2x*u2x + u2y*u2y + EPSf);
    float f1 = 1.0f / (1.0f + taut * n1);
    float f2 = 1.0f / (1.0f + taut * n2);
    o11 = (p11 + taut * u1x) * f1;
    o12 = (p12 + taut * u1y) * f1;
    o21 = (p21 + taut * u2x) * f2;
    o22 = (p22 + taut * u2y) * f2;
}

// vector u-update for one float4 group
__device__ __forceinline__ void u_vec(
    const F4& U1, const F4& U2, const F4& GX, const F4& GY, const F4& RC,
    const F4& Q11, const F4& Q12, const F4& Q21, const F4& Q22,
    float q11L, float q21L, const F4& P12U, const F4& P22U,
    int jbase, bool i0, float ts, float l_t, F4& O1, F4& O2)
{
#pragma unroll
    for (int k = 0; k < 4; k++) {
        float l11 = (k > 0) ? Q11.f[k-1] : q11L;
        float l21 = (k > 0) ? Q21.f[k-1] : q21L;
        u_lane(U1.f[k], U2.f[k], GX.f[k], GY.f[k], RC.f[k],
               Q11.f[k], l11, Q12.f[k], P12U.f[k],
               Q21.f[k], l21, Q22.f[k], P22U.f[k],
               (jbase + k) == 0, i0, ts, l_t, O1.f[k], O2.f[k]);
    }
}

// vector p-update for one float4 group (U = u' at this row, D = u' at row below)
__device__ __forceinline__ void p_vec(
    const F4& U1, const F4& U2, float u1R, float u2R,
    const F4& D1, const F4& D2,
    const F4& Q11, const F4& Q12, const F4& Q21, const F4& Q22,
    int jbase, bool hasD, float taut,
    F4& O11, F4& O12, F4& O21, F4& O22)
{
#pragma unroll
    for (int k = 0; k < 4; k++) {
        float uR1 = (k < 3) ? U1.f[k+1] : u1R;
        float uR2 = (k < 3) ? U2.f[k+1] : u2R;
        p_lane(U1.f[k], uR1, D1.f[k], U2.f[k], uR2, D2.f[k],
               (jbase + k) < Wd - 1, hasD, taut,
               Q11.f[k], Q12.f[k], Q21.f[k], Q22.f[k],
               O11.f[k], O12.f[k], O21.f[k], O22.f[k]);
    }
}

// ============================================================================
// Init (per half): g2x, g2y (centered grads of y, x boundary rows/cols), rc.
// ============================================================================
__global__ void __launch_bounds__(256) k_init(
    const float* __restrict__ x, const float* __restrict__ y, int off)
{
    int v = blockIdx.x * blockDim.x + threadIdx.x;
    if (v >= NVH) return;
    int il = v << 2;
    int idx = il + off;
    int j4 = il & (Wd - 1);
    int i  = (il >> 8) & (Hd - 1);

    F4 X, Y, Yu, Yd, Xu, Xd;
    X.v = ld4(x + idx);
    Y.v = ld4(y + idx);
    float yl = (j4 > 0)       ? y[idx - 1] : 0.f;
    float yr = (j4 + 4 < Wd)  ? y[idx + 4] : 0.f;
    Yu.v = (i > 0)      ? ld4(y + idx - Wd) : make_float4(0,0,0,0);
    Yd.v = (i < Hd - 1) ? ld4(y + idx + Wd) : make_float4(0,0,0,0);
    Xd.v = (i == 0)      ? ld4(x + idx + Wd) : make_float4(0,0,0,0);
    Xu.v = (i == Hd - 1) ? ld4(x + idx - Wd) : make_float4(0,0,0,0);

    F4 GX, GY, RC;
#pragma unroll
    for (int k = 0; k < 4; k++) {
        int j = j4 + k;
        float gx;
        if (j == 0)            gx = 0.5f * (X.f[1] - X.f[0]);
        else if (j == Wd - 1)  gx = 0.5f * (X.f[3] - X.f[2]);
        else {
            float yn = (k < 3) ? Y.f[k + 1] : yr;
            float yp = (k > 0) ? Y.f[k - 1] : yl;
            gx = 0.5f * (yn - yp);
        }
        float gy;
        if (i == 0)            gy = 0.5f * (Xd.f[k] - X.f[k]);
        else if (i == Hd - 1)  gy = 0.5f * (X.f[k] - Xu.f[k]);
        else                   gy = 0.5f * (Yd.f[k] - Yu.f[k]);
        GX.f[k] = gx; GY.f[k] = gy; RC.f[k] = Y.f[k] - X.f[k];
    }
    st4(g_g2x + idx, GX.v);
    st4(g_g2y + idx, GY.v);
    st4(g_rc  + idx, RC.v);
}

// ============================================================================
// One iteration (U_k then P_k), warp-autonomous column sweep.
// Warp = 256-col strip of SEG rows: lane owns cols [4L,4L+3] (grp A) and
// [128+4L,128+4L+3] (grp B). All halo exchange via shfl. No smem, no syncs.
// ============================================================================
template<bool FIRST, bool LAST, int PRD, int PWR>
__global__ void __launch_bounds__(128) k_iter(
    const float* __restrict__ tp, const float* __restrict__ lp,
    const float* __restrict__ ap,
    const float* __restrict__ u1r, const float* __restrict__ u2r,
    float* __restrict__ u1w, float* __restrict__ u2w, int off)
{
    const int lane  = threadIdx.x & 31;
    const int strip = blockIdx.x * 4 + (threadIdx.x >> 5);
    const int nseg  = Hd / SEG;
    const int img   = strip / nseg;
    const int seg   = strip % nseg;
    const int r0 = seg * SEG, r1 = r0 + SEG;
    const int base = off + img * (Hd * Wd);
    const int ca = 4 * lane;
    const int cb = 128 + 4 * lane;

    const float ts   = tp[0];
    const float l_t  = lp[0] * ts;
    const float taut = ap[0] / ts;

    const float* __restrict__ P11r = g_p11[PRD];
    const float* __restrict__ P12r = g_p12[PRD];
    const float* __restrict__ P21r = g_p21[PRD];
    const float* __restrict__ P22r = g_p22[PRD];
    float* __restrict__ P11w = g_p11[PWR];
    float* __restrict__ P12w = g_p12[PWR];
    float* __restrict__ P21w = g_p21[PWR];
    float* __restrict__ P22w = g_p22[PWR];

    // up-halo carries p_old(i-1) for fields 12/22
    F4 pc12a = zf4(), pc22a = zf4(), pc12b = zf4(), pc22b = zf4();
    if (!FIRST && r0 > 0) {
        int oA = base + (r0 - 1) * Wd + ca, oB = oA + 128;
        pc12a.v = ld4(P12r + oA); pc22a.v = ld4(P22r + oA);
        pc12b.v = ld4(P12r + oB); pc22b.v = ld4(P22r + oB);
    }
    // u'(i-1) carries + their right-neighbor scalars
    F4 up1a = zf4(), up2a = zf4(), up1b = zf4(), up2b = zf4();
    float ur1a_p = 0.f, ur2a_p = 0.f, ur1b_p = 0.f, ur2b_p = 0.f;

#pragma unroll 1
    for (int i = r0; i < r1; ++i) {
        int oA = base + i * Wd + ca, oB = oA + 128;

        F4 U1a, U2a, U1b, U2b;
        F4 Q11a, Q12a, Q21a, Q22a, Q11b, Q12b, Q21b, Q22b;
        if (!FIRST) {
            U1a.v = ld4(u1r + oA); U2a.v = ld4(u2r + oA);
            U1b.v = ld4(u1r + oB); U2b.v = ld4(u2r + oB);
            Q11a.v = ld4(P11r + oA); Q12a.v = ld4(P12r + oA);
            Q21a.v = ld4(P21r + oA); Q22a.v = ld4(P22r + oA);
            Q11b.v = ld4(P11r + oB); Q12b.v = ld4(P12r + oB);
            Q21b.v = ld4(P21r + oB); Q22b.v = ld4(P22r + oB);
        } else {
            U1a = U2a = U1b = U2b = zf4();
            Q11a = Q12a = Q21a = Q22a = zf4();
            Q11b = Q12b = Q21b = Q22b = zf4();
        }
        F4 GXa, GYa, RCa, GXb, GYb, RCb;
        GXa.v = ld4(g_g2x + oA); GYa.v = ld4(g_g2y + oA); RCa.v = ld4(g_rc + oA);
        GXb.v = ld4(g_g2x + oB); GYb.v = ld4(g_g2y + oB); RCb.v = ld4(g_rc + oB);

        // left p_old halos via shfl (grp B lane0 wraps to grp A lane31)
        float l11a = __shfl_up_sync(FULLM, Q11a.f[3], 1);
        float l21a = __shfl_up_sync(FULLM, Q21a.f[3], 1);
        float w11  = __shfl_sync(FULLM, Q11a.f[3], 31);
        float w21  = __shfl_sync(FULLM, Q21a.f[3], 31);
        float l11b = __shfl_up_sync(FULLM, Q11b.f[3], 1);
        float l21b = __shfl_up_sync(FULLM, Q21b.f[3], 1);
        if (lane == 0) { l11b = w11; l21b = w21; }

        bool i0 = (i == 0);
        F4 uc1a, uc2a, uc1b, uc2b;
        u_vec(U1a, U2a, GXa, GYa, RCa, Q11a, Q12a, Q21a, Q22a,
              l11a, l21a, pc12a, pc22a, ca, i0, ts, l_t, uc1a, uc2a);
        u_vec(U1b, U2b, GXb, GYb, RCb, Q11b, Q12b, Q21b, Q22b,
              l11b, l21b, pc12b, pc22b, cb, i0, ts, l_t, uc1b, uc2b);

        // right u' halos via shfl (grp A lane31 wraps to grp B lane0)
        float ra1 = __shfl_down_sync(FULLM, uc1a.f[0], 1);
        float ra2 = __shfl_down_sync(FULLM, uc2a.f[0], 1);
        float fb1 = __shfl_sync(FULLM, uc1b.f[0], 0);
        float fb2 = __shfl_sync(FULLM, uc2b.f[0], 0);
        float ur1a = (lane == 31) ? fb1 : ra1;
        float ur2a = (lane == 31) ? fb2 : ra2;
        float ur1b = __shfl_down_sync(FULLM, uc1b.f[0], 1);
        float ur2b = __shfl_down_sync(FULLM, uc2b.f[0], 1);

        // emit p'(i-1): u'(i-1)=carries, uD=current u'; p_old(i-1) reloaded (L1 hit)
        if (!LAST && i > r0) {
            int eA = oA - Wd, eB = oB - Wd;
            F4 pe11a, pe12a, pe21a, pe22a, pe11b, pe12b, pe21b, pe22b;
            if (!FIRST) {
                pe11a.v = ld4(P11r + eA); pe12a.v = ld4(P12r + eA);
                pe21a.v = ld4(P21r + eA); pe22a.v = ld4(P22r + eA);
                pe11b.v = ld4(P11r + eB); pe12b.v = ld4(P12r + eB);
                pe21b.v = ld4(P21r + eB); pe22b.v = ld4(P22r + eB);
            } else {
                pe11a = pe12a = pe21a = pe22a = zf4();
                pe11b = pe12b = pe21b = pe22b = zf4();
            }
            F4 n11, n12, n21, n22;
            p_vec(up1a, up2a, ur1a_p, ur2a_p, uc1a, uc2a,
                  pe11a, pe12a, pe21a, pe22a, ca, true, taut, n11, n12, n21, n22);
            st4(P11w + eA, n11.v); st4(P12w + eA, n12.v);
            st4(P21w + eA, n21.v); st4(P22w + eA, n22.v);
            p_vec(up1b, up2b, ur1b_p, ur2b_p, uc1b, uc2b,
                  pe11b, pe12b, pe21b, pe22b, cb, true, taut, n11, n12, n21, n22);
            st4(P11w + eB, n11.v); st4(P12w + eB, n12.v);
            st4(P21w + eB, n21.v); st4(P22w + eB, n22.v);
        }

        st4(u1w + oA, uc1a.v); st4(u2w + oA, uc2a.v);
        st4(u1w + oB, uc1b.v); st4(u2w + oB, uc2b.v);

        up1a = uc1a; up2a = uc2a; up1b = uc1b; up2b = uc2b;
        ur1a_p = ur1a; ur2a_p = ur2a; ur1b_p = ur1b; ur2b_p = ur2b;
        pc12a = Q12a; pc22a = Q22a; pc12b = Q12b; pc22b = Q22b;
    }

    // epilogue: emit p'(r1-1); needs u'(r1) recompute if r1 < H
    if (!LAST) {
        bool hasD = (r1 < Hd);
        F4 d1a = zf4(), d2a = zf4(), d1b = zf4(), d2b = zf4();
        if (hasD) {
            int oA = base + r1 * Wd + ca, oB = oA + 128;
            F4 U1a, U2a, U1b, U2b;
            F4 Q11a, Q12a, Q21a, Q22a, Q11b, Q12b, Q21b, Q22b;
            if (!FIRST) {
                U1a.v = ld4(u1r + oA); U2a.v = ld4(u2r + oA);
                U1b.v = ld4(u1r + oB); U2b.v = ld4(u2r + oB);
                Q11a.v = ld4(P11r + oA); Q12a.v = ld4(P12r + oA);
                Q21a.v = ld4(P21r + oA); Q22a.v = ld4(P22r + oA);
                Q11b.v = ld4(P11r + oB); Q12b.v = ld4(P12r + oB);
                Q21b.v = ld4(P21r + oB); Q22b.v = ld4(P22r + oB);
            } else {
                U1a = U2a = U1b = U2b = zf4();
                Q11a = Q12a = Q21a = Q22a = zf4();
                Q11b = Q12b = Q21b = Q22b = zf4();
            }
            F4 GXa, GYa, RCa, GXb, GYb, RCb;
            GXa.v = ld4(g_g2x + oA); GYa.v = ld4(g_g2y + oA); RCa.v = ld4(g_rc + oA);
            GXb.v = ld4(g_g2x + oB); GYb.v = ld4(g_g2y + oB); RCb.v = ld4(g_rc + oB);

            float l11a = __shfl_up_sync(FULLM, Q11a.f[3], 1);
            float l21a = __shfl_up_sync(FULLM, Q21a.f[3], 1);
            float w11  = __shfl_sync(FULLM, Q11a.f[3], 31);
            float w21  = __shfl_sync(FULLM, Q21a.f[3], 31);
            float l11b = __shfl_up_sync(FULLM, Q11b.f[3], 1);
            float l21b = __shfl_up_sync(FULLM, Q21b.f[3], 1);
            if (lane == 0) { l11b = w11; l21b = w21; }

            u_vec(U1a, U2a, GXa, GYa, RCa, Q11a, Q12a, Q21a, Q22a,
                  l11a, l21a, pc12a, pc22a, ca, false, ts, l_t, d1a, d2a);
            u_vec(U1b, U2b, GXb, GYb, RCb, Q11b, Q12b, Q21b, Q22b,
                  l11b, l21b, pc12b, pc22b, cb, false, ts, l_t, d1b, d2b);
        }
        int eA = base + (r1 - 1) * Wd + ca, eB = eA + 128;
        F4 pe11a, pe12a, pe21a, pe22a, pe11b, pe12b, pe21b, pe22b;
        if (!FIRST) {
            pe11a.v = ld4(P11r + eA); pe12a.v = ld4(P12r + eA);
            pe21a.v = ld4(P21r + eA); pe22a.v = ld4(P22r + eA);
            pe11b.v = ld4(P11r + eB); pe12b.v = ld4(P12r + eB);
            pe21b.v = ld4(P21r + eB); pe22b.v = ld4(P22r + eB);
        } else {
            pe11a = pe12a = pe21a = pe22a = zf4();
            pe11b = pe12b = pe21b = pe22b = zf4();
        }
        F4 n11, n12, n21, n22;
        p_vec(up1a, up2a, ur1a_p, ur2a_p, d1a, d2a,
              pe11a, pe12a, pe21a, pe22a, ca, hasD, taut, n11, n12, n21, n22);
        st4(P11w + eA, n11.v); st4(P12w + eA, n12.v);
        st4(P21w + eA, n21.v); st4(P22w + eA, n22.v);
        p_vec(up1b, up2b, ur1b_p, ur2b_p, d1b, d2b,
              pe11b, pe12b, pe21b, pe22b, cb, hasD, taut, n11, n12, n21, n22);
        st4(P11w + eB, n11.v); st4(P12w + eB, n12.v);
        st4(P21w + eB, n21.v); st4(P22w + eB, n22.v);
    }
}

// ============================================================================
// Schedule per half: init(g); iter1 FIRST -> S,p0; alternate; iter10 LAST -> D.
// ============================================================================
extern "C" void kernel_launch(void* const* d_in, const int* in_sizes, int n_in,
                              void* d_out, int out_size)
{
    const float* x = (const float*)d_in[0];
    const float* y = (const float*)d_in[1];
    const float* t = (const float*)d_in[8];
    const float* l = (const float*)d_in[9];
    const float* a = (const float*)d_in[10];

    float* ud1 = (float*)d_out;
    float* ud2 = ud1 + NPIX;

    float* us1; cudaGetSymbolAddress((void**)&us1, g_u1s);
    float* us2; cudaGetSymbolAddress((void**)&us2, g_u2s);

    const int blocksI = (NVH + 255) / 256;
    const int strips  = HIMG * (Hd / SEG);
    const int blocksK = strips / 4;      // 4 warps per block

    for (int h = 0; h < 2; ++h) {
        int off = h * HPIX;
        k_init<<<blocksI, 256>>>(x, y, off);
        k_iter<true,  false, 0, 0><<<blocksK, 128>>>(t, l, a, us1, us2, us1, us2, off); // it1 -> S, p0
        k_iter<false, false, 0, 1><<<blocksK, 128>>>(t, l, a, us1, us2, ud1, ud2, off); // it2 S->D
        k_iter<false, false, 1, 0><<<blocksK, 128>>>(t, l, a, ud1, ud2, us1, us2, off); // it3 D->S
        k_iter<false, false, 0, 1><<<blocksK, 128>>>(t, l, a, us1, us2, ud1, ud2, off); // it4 S->D
        k_iter<false, false, 1, 0><<<blocksK, 128>>>(t, l, a, ud1, ud2, us1, us2, off); // it5 D->S
        k_iter<false, false, 0, 1><<<blocksK, 128>>>(t, l, a, us1, us2, ud1, ud2, off); // it6 S->D
        k_iter<false, false, 1, 0><<<blocksK, 128>>>(t, l, a, ud1, ud2, us1, us2, off); // it7 D->S
        k_iter<false, false, 0, 1><<<blocksK, 128>>>(t, l, a, us1, us2, ud1, ud2, off); // it8 S->D
        k_iter<false, false, 1, 0><<<blocksK, 128>>>(t, l, a, ud1, ud2, us1, us2, off); // it9 D->S
        k_iter<false, true,  0, 0><<<blocksK, 128>>>(t, l, a, us1, us2, ud1, ud2, off); // it10 S->D (LAST)
    }
}

// round 9
// speedup vs baseline: 1.4068x; 1.4068x over previous
#include <cuda_runtime.h>

#define Wd 256
#define Hd 256
#define Bd 64
#define NPIX (Bd*Hd*Wd)
#define QIMG 16
#define QPIX (QIMG*Hd*Wd)
#define NVQ  (QPIX/4)
#define TX 64
#define TY 16
#define SS 68              // smem row stride (floats): 17 vecs
#define EPSf 1e-12f

// ---- iteration-invariant scratch ----
__device__ __align__(16) float g_g2x[NPIX];
__device__ __align__(16) float g_g2y[NPIX];
__device__ __align__(16) float g_rc [NPIX];
// ---- double-buffered dual state ----
__device__ __align__(16) float g_p11[2][NPIX];
__device__ __align__(16) float g_p12[2][NPIX];
__device__ __align__(16) float g_p21[2][NPIX];
__device__ __align__(16) float g_p22[2][NPIX];
// ---- u scratch (ping-pongs with d_out) ----
__device__ __align__(16) float g_u1s[NPIX];
__device__ __align__(16) float g_u2s[NPIX];

union F4 { float4 v; float f[4]; };
__device__ __forceinline__ float4 ld4(const float* p) { return *reinterpret_cast<const float4*>(p); }
__device__ __forceinline__ void   st4(float* p, float4 v) { *reinterpret_cast<float4*>(p) = v; }
__device__ __forceinline__ F4 zf4() { F4 a; a.v = make_float4(0,0,0,0); return a; }

// u' = u + v(u) + ts*div(p)   (one pixel)
__device__ __forceinline__ void u_lane(
    float u1, float u2, float gx, float gy, float rc,
    float p11, float p11L, float p12, float p12U,
    float p21, float p21L, float p22, float p22U,
    bool j0, bool i0, float ts, float l_t,
    float& o1, float& o2)
{
    float dx1 = j0 ? p11 : (p11 - p11L);
    float dx2 = j0 ? p21 : (p21 - p21L);
    float dy1 = i0 ? p12 : (p12 - p12U);
    float dy2 = i0 ? p22 : (p22 - p22U);
    float rho  = rc + gx * u1 + gy * u2 + EPSf;
    float grad = gx * gx + gy * gy + EPSf;
    float lg   = l_t * grad;
    float v1, v2;
    if      (rho < -lg)   { v1 =  l_t * gx; v2 =  l_t * gy; }
    else if (rho >  lg)   { v1 = -l_t * gx; v2 = -l_t * gy; }
    else if (grad > EPSf) { float s = -rho / grad; v1 = s * gx; v2 = s * gy; }
    else                  { v1 = 0.f; v2 = 0.f; }
    o1 = u1 + v1 + ts * (dx1 + dy1);
    o2 = u2 + v2 + ts * (dx2 + dy2);
}

// p' = (p + taut*grad_u) / (1 + taut*|grad_u|)   (one pixel)
__device__ __forceinline__ void p_lane(
    float uC1, float uR1, float uD1, float uC2, float uR2, float uD2,
    bool hasR, bool hasD, float taut,
    float p11, float p12, float p21, float p22,
    float& o11, float& o12, float& o21, float& o22)
{
    float u1x = hasR ? (uR1 - uC1) : 0.f;
    float u2x = hasR ? (uR2 - uC2) : 0.f;
    float u1y = hasD ? (uD1 - uC1) : 0.f;
    float u2y = hasD ? (uD2 - uC2) : 0.f;
    float n1 = sqrtf(u1x*u1x + u1y*u1y + EPSf);
    float n2 = sqrtf(u2x*u2x + u2y*u2y + EPSf);
    float f1 = 1.0f / (1.0f + taut * n1);
    float f2 = 1.0f / (1.0f + taut * n2);
    o11 = (p11 + taut * u1x) * f1;
    o12 = (p12 + taut * u1y) * f1;
    o21 = (p21 + taut * u2x) * f2;
    o22 = (p22 + taut * u2y) * f2;
}

// ============================================================================
// Init (per quarter): g2x, g2y (centered grads of y, x boundary), rc = y - x.
// ============================================================================
__global__ void __launch_bounds__(256) k_init(
    const float* __restrict__ x, const float* __restrict__ y, int off)
{
    int v = blockIdx.x * blockDim.x + threadIdx.x;
    if (v >= NVQ) return;
    int il = v << 2;
    int idx = il + off;
    int j4 = il & (Wd - 1);
    int i  = (il >> 8) & (Hd - 1);

    F4 X, Y, Yu, Yd, Xu, Xd;
    X.v = ld4(x + idx);
    Y.v = ld4(y + idx);
    float yl = (j4 > 0)       ? y[idx - 1] : 0.f;
    float yr = (j4 + 4 < Wd)  ? y[idx + 4] : 0.f;
    Yu.v = (i > 0)      ? ld4(y + idx - Wd) : make_float4(0,0,0,0);
    Yd.v = (i < Hd - 1) ? ld4(y + idx + Wd) : make_float4(0,0,0,0);
    Xd.v = (i == 0)      ? ld4(x + idx + Wd) : make_float4(0,0,0,0);
    Xu.v = (i == Hd - 1) ? ld4(x + idx - Wd) : make_float4(0,0,0,0);

    F4 GX, GY, RC;
#pragma unroll
    for (int k = 0; k < 4; k++) {
        int j = j4 + k;
        float gx;
        if (j == 0)            gx = 0.5f * (X.f[1] - X.f[0]);
        else if (j == Wd - 1)  gx = 0.5f * (X.f[3] - X.f[2]);
        else {
            float yn = (k < 3) ? Y.f[k + 1] : yr;
            float yp = (k > 0) ? Y.f[k - 1] : yl;
            gx = 0.5f * (yn - yp);
        }
        float gy;
        if (i == 0)            gy = 0.5f * (Xd.f[k] - X.f[k]);
        else if (i == Hd - 1)  gy = 0.5f * (X.f[k] - Xu.f[k]);
        else                   gy = 0.5f * (Yd.f[k] - Yu.f[k]);
        GX.f[k] = gx; GY.f[k] = gy; RC.f[k] = Y.f[k] - X.f[k];
    }
    st4(g_g2x + idx, GX.v);
    st4(g_g2y + idx, GY.v);
    st4(g_rc  + idx, RC.v);
}

// ============================================================================
// Fused iteration k: U_k (u_{k-1}, p_{k-1}) then P_k (u_k, p_{k-1}).
// Stage 1: compute u' on extended tile (17 rows x 17 vecs; all inputs are
//          global loads), store center to global u-out, all to smem.
// Stage 2: p' on center from smem u' + reloaded p_old (L1 hit) -> global.
// Double-buffered u and p => race-free. FIRST: u=p=0. LAST: stage 2 skipped.
// ============================================================================
template<bool FIRST, bool LAST, int PRD, int PWR>
__global__ void __launch_bounds__(256) k_fused(
    const float* __restrict__ tp, const float* __restrict__ lp,
    const float* __restrict__ ap,
    const float* __restrict__ u1r, const float* __restrict__ u2r,
    float* __restrict__ u1w, float* __restrict__ u2w, int off)
{
    __shared__ __align__(16) float sU1[17*SS], sU2[17*SS];

    const int tid = threadIdx.x;
    const int tx0 = blockIdx.x * TX;
    const int ty0 = blockIdx.y * TY;
    const int base = off + blockIdx.z * (Hd * Wd);

    const float ts   = tp[0];
    const float l_t  = lp[0] * ts;
    const float taut = ap[0] / ts;

    const float* __restrict__ P11r = g_p11[PRD];
    const float* __restrict__ P12r = g_p12[PRD];
    const float* __restrict__ P21r = g_p21[PRD];
    const float* __restrict__ P22r = g_p22[PRD];

    // ---- stage 1: u' on extended region ----
    const int NT = LAST ? 256 : (17*17);
#pragma unroll 1
    for (int t = tid; t < NT; t += 256) {
        int r, v;
        if (LAST) { r = t >> 4; v = t & 15; }
        else      { r = t / 17; v = t % 17; }
        int grow = ty0 + r;
        int gcol = tx0 + 4*v;
        bool valid = (grow < Hd) && (gcol < Wd);

        F4 O1 = zf4(), O2 = zf4();
        if (valid) {
            int o = base + grow * Wd + gcol;
            F4 U1 = zf4(), U2 = zf4();
            F4 Q11 = zf4(), Q12 = zf4(), Q21 = zf4(), Q22 = zf4();
            F4 P12u = zf4(), P22u = zf4();
            float l11 = 0.f, l21 = 0.f;
            if (!FIRST) {
                U1.v = ld4(u1r + o); U2.v = ld4(u2r + o);
                Q11.v = ld4(P11r + o); Q12.v = ld4(P12r + o);
                Q21.v = ld4(P21r + o); Q22.v = ld4(P22r + o);
                if (grow > 0) {
                    P12u.v = ld4(P12r + o - Wd);
                    P22u.v = ld4(P22r + o - Wd);
                }
                if (gcol > 0) { l11 = P11r[o - 1]; l21 = P21r[o - 1]; }
            }
            F4 GX, GY, RC;
            GX.v = ld4(g_g2x + o); GY.v = ld4(g_g2y + o); RC.v = ld4(g_rc + o);

            bool i0 = (grow == 0);
#pragma unroll
            for (int k = 0; k < 4; k++) {
                float pl11 = (k > 0) ? Q11.f[k-1] : l11;
                float pl21 = (k > 0) ? Q21.f[k-1] : l21;
                u_lane(U1.f[k], U2.f[k], GX.f[k], GY.f[k], RC.f[k],
                       Q11.f[k], pl11, Q12.f[k], P12u.f[k],
                       Q21.f[k], pl21, Q22.f[k], P22u.f[k],
                       (gcol + k) == 0, i0, ts, l_t, O1.f[k], O2.f[k]);
            }
            if (r < TY && v < 16) {      // center tile -> global u-out
                st4(u1w + o, O1.v);
                st4(u2w + o, O2.v);
            }
        }
        if (!LAST) {
            st4(sU1 + r*SS + 4*v, O1.v);
            st4(sU2 + r*SS + 4*v, O2.v);
        }
    }

    if (LAST) return;
    __syncthreads();

    // ---- stage 2: p' on center from smem u' ----
    {
        int r = tid >> 4, v = tid & 15;
        int grow = ty0 + r;
        int gcol = tx0 + 4*v;
        int o = base + grow * Wd + gcol;
        int s = r*SS + 4*v;

        F4 U1c, U2c, U1d, U2d;
        U1c.v = *(float4*)(sU1 + s);      U2c.v = *(float4*)(sU2 + s);
        U1d.v = *(float4*)(sU1 + s + SS); U2d.v = *(float4*)(sU2 + s + SS);
        float u1R = sU1[s + 4];
        float u2R = sU2[s + 4];

        F4 Q11 = zf4(), Q12 = zf4(), Q21 = zf4(), Q22 = zf4();
        if (!FIRST) {   // reload p_old: L1 hit (loaded by this block in stage 1)
            Q11.v = ld4(P11r + o); Q12.v = ld4(P12r + o);
            Q21.v = ld4(P21r + o); Q22.v = ld4(P22r + o);
        }

        bool hasD = (grow < Hd - 1);
        F4 N11, N12, N21, N22;
#pragma unroll
        for (int k = 0; k < 4; k++) {
            int j = gcol + k;
            float uR1 = (k < 3) ? U1c.f[k+1] : u1R;
            float uR2 = (k < 3) ? U2c.f[k+1] : u2R;
            p_lane(U1c.f[k], uR1, U1d.f[k], U2c.f[k], uR2, U2d.f[k],
                   (j < Wd - 1), hasD, taut,
                   Q11.f[k], Q12.f[k], Q21.f[k], Q22.f[k],
                   N11.f[k], N12.f[k], N21.f[k], N22.f[k]);
        }
        st4(g_p11[PWR] + o, N11.v);
        st4(g_p12[PWR] + o, N12.v);
        st4(g_p21[PWR] + o, N21.v);
        st4(g_p22[PWR] + o, N22.v);
    }
}

// ============================================================================
// Schedule per quarter: init(g); 10 fused iterations.
// u buffers: iter1->S, then ping-pong; iter10 -> d_out.
// p sets:    iter1 w0; iter2 r0 w1; ...; iter9 w0; iter10 r0 (LAST, no write).
// ============================================================================
extern "C" void kernel_launch(void* const* d_in, const int* in_sizes, int n_in,
                              void* d_out, int out_size)
{
    const float* x = (const float*)d_in[0];
    const float* y = (const float*)d_in[1];
    const float* t = (const float*)d_in[8];
    const float* l = (const float*)d_in[9];
    const float* a = (const float*)d_in[10];

    float* ud1 = (float*)d_out;
    float* ud2 = ud1 + NPIX;

    float* us1; cudaGetSymbolAddress((void**)&us1, g_u1s);
    float* us2; cudaGetSymbolAddress((void**)&us2, g_u2s);

    const int blocksI = (NVQ + 255) / 256;
    dim3 grid(Wd / TX, Hd / TY, QIMG);

    for (int q = 0; q < 4; ++q) {
        int off = q * QPIX;
        k_init<<<blocksI, 256>>>(x, y, off);
        k_fused<true,  false, 0, 0><<<grid, 256>>>(t, l, a, us1, us2, us1, us2, off); // it1  -> S, p w0
        k_fused<false, false, 0, 1><<<grid, 256>>>(t, l, a, us1, us2, ud1, ud2, off); // it2  S->D, r0 w1
        k_fused<false, false, 1, 0><<<grid, 256>>>(t, l, a, ud1, ud2, us1, us2, off); // it3  D->S, r1 w0
        k_fused<false, false, 0, 1><<<grid, 256>>>(t, l, a, us1, us2, ud1, ud2, off); // it4  S->D
        k_fused<false, false, 1, 0><<<grid, 256>>>(t, l, a, ud1, ud2, us1, us2, off); // it5  D->S
        k_fused<false, false, 0, 1><<<grid, 256>>>(t, l, a, us1, us2, ud1, ud2, off); // it6  S->D
        k_fused<false, false, 1, 0><<<grid, 256>>>(t, l, a, ud1, ud2, us1, us2, off); // it7  D->S
        k_fused<false, false, 0, 1><<<grid, 256>>>(t, l, a, us1, us2, ud1, ud2, off); // it8  S->D
        k_fused<false, false, 1, 0><<<grid, 256>>>(t, l, a, ud1, ud2, us1, us2, off); // it9  D->S, w0
        k_fused<false, true,  0, 0><<<grid, 256>>>(t, l, a, us1, us2, ud1, ud2, off); // it10 S->D (LAST, r0)
    }
}